// round 1
// baseline (speedup 1.0000x reference)
#include <cuda_runtime.h>

#define NN 200000
#define NE 2000000
#define NG 10000

// -------- scratch (static device globals; no allocation) --------
__device__ float d_h[NN * 32];
__device__ float d_z[NN * 32];
__device__ float d_z2[NN * 32];
__device__ float d_pool[NG * 32];
__device__ float d_cnt[NG];
__device__ float d_bnstat[2 * 64];   // per layer: [sum(32) | sumsq(32)]
__device__ float d_bnscale[2 * 64];  // per layer: [scale(32) | shift(32)]

// -------- zero accumulators --------
__global__ void k_zero() {
    int i = blockIdx.x * blockDim.x + threadIdx.x;
    const int n = NG * 32 + NG + 2 * 64;
    for (; i < n; i += gridDim.x * blockDim.x) {
        if (i < NG * 32) d_pool[i] = 0.f;
        else if (i < NG * 32 + NG) d_cnt[i - NG * 32] = 0.f;
        else d_bnstat[i - NG * 32 - NG] = 0.f;
    }
}

// -------- node embedding: h = x @ node_w + node_b ; also z = h --------
__global__ void k_embed(const float* __restrict__ x,
                        const float* __restrict__ nw,
                        const float* __restrict__ nb) {
    __shared__ float w[14 * 32];
    __shared__ float b[32];
    for (int i = threadIdx.x; i < 448; i += blockDim.x) w[i] = nw[i];
    if (threadIdx.x < 32) b[threadIdx.x] = nb[threadIdx.x];
    __syncthreads();
    int n = blockIdx.x * blockDim.x + threadIdx.x;
    if (n >= NN) return;
    float xv[14];
#pragma unroll
    for (int k = 0; k < 14; k++) xv[k] = x[n * 14 + k];
#pragma unroll
    for (int f = 0; f < 32; f++) {
        float o = b[f];
#pragma unroll
        for (int k = 0; k < 14; k++) o += xv[k] * w[k * 32 + f];
        d_h[n * 32 + f] = o;
        d_z[n * 32 + f] = o;
    }
}

// -------- edge messages: z[dst] += relu(h[src] + attr@ew + eb) --------
// 8 lanes per edge, 4 features per lane, vector reduction atomics.
__global__ void k_edge(const int* __restrict__ ei,
                       const float* __restrict__ ea,
                       const float* __restrict__ ew,
                       const float* __restrict__ eb) {
    __shared__ float w[96];
    __shared__ float b[32];
    for (int i = threadIdx.x; i < 96; i += blockDim.x) w[i] = ew[i];
    if (threadIdx.x < 32) b[threadIdx.x] = eb[threadIdx.x];
    __syncthreads();
    int t = blockIdx.x * blockDim.x + threadIdx.x;
    int e = t >> 3;
    if (e >= NE) return;
    int q = t & 7;
    int f0 = q * 4;
    int src = __ldg(ei + e);
    int dst = __ldg(ei + NE + e);
    float a0 = __ldg(ea + e * 3 + 0);
    float a1 = __ldg(ea + e * 3 + 1);
    float a2 = __ldg(ea + e * 3 + 2);
    float4 hv = *(const float4*)(d_h + src * 32 + f0);
    float m0 = fmaxf(0.f, hv.x + b[f0 + 0] + a0 * w[f0 + 0] + a1 * w[32 + f0 + 0] + a2 * w[64 + f0 + 0]);
    float m1 = fmaxf(0.f, hv.y + b[f0 + 1] + a0 * w[f0 + 1] + a1 * w[32 + f0 + 1] + a2 * w[64 + f0 + 1]);
    float m2 = fmaxf(0.f, hv.z + b[f0 + 2] + a0 * w[f0 + 2] + a1 * w[32 + f0 + 2] + a2 * w[64 + f0 + 2]);
    float m3 = fmaxf(0.f, hv.w + b[f0 + 3] + a0 * w[f0 + 3] + a1 * w[32 + f0 + 3] + a2 * w[64 + f0 + 3]);
    float* p = d_z + dst * 32 + f0;
    asm volatile("red.global.add.v4.f32 [%0], {%1,%2,%3,%4};"
                 :: "l"(p), "f"(m0), "f"(m1), "f"(m2), "f"(m3) : "memory");
}

// -------- MLP: z2 = relu(z@W1+b1)@W2+b2, fused BN partial sums --------
__global__ void __launch_bounds__(128) k_mlp(int l,
        const float* __restrict__ w1, const float* __restrict__ b1,
        const float* __restrict__ w2, const float* __restrict__ b2) {
    __shared__ float W1[32 * 75];
    __shared__ float B1[75];
    __shared__ float W2[75 * 32];
    __shared__ float zs[128 * 33];
    __shared__ float ssum[32], ssq[32];
    const float* w1l = w1 + l * 2400;
    const float* w2l = w2 + l * 2400;
    for (int i = threadIdx.x; i < 2400; i += 128) { W1[i] = w1l[i]; W2[i] = w2l[i]; }
    for (int i = threadIdx.x; i < 75; i += 128) B1[i] = b1[l * 75 + i];
    if (threadIdx.x < 32) { ssum[threadIdx.x] = 0.f; ssq[threadIdx.x] = 0.f; }
    int base = blockIdx.x * 128;
    int rows = min(128, NN - base);
    for (int i = threadIdx.x; i < rows * 32; i += 128)
        zs[(i >> 5) * 33 + (i & 31)] = d_z[base * 32 + i];
    __syncthreads();
    int tid = threadIdx.x;
    float acc[32];
    if (tid < rows) {
        float zr[32];
#pragma unroll
        for (int k = 0; k < 32; k++) zr[k] = zs[tid * 33 + k];
#pragma unroll
        for (int f = 0; f < 32; f++) acc[f] = __ldg(b2 + l * 32 + f);
        for (int j = 0; j < 75; j++) {
            float hj = B1[j];
#pragma unroll
            for (int k = 0; k < 32; k++) hj += zr[k] * W1[k * 75 + j];
            hj = fmaxf(hj, 0.f);
#pragma unroll
            for (int f = 0; f < 32; f++) acc[f] += hj * W2[j * 32 + f];
        }
    }
    __syncthreads();
    if (tid < rows) {
#pragma unroll
        for (int f = 0; f < 32; f++) zs[tid * 33 + f] = acc[f];
    }
    __syncthreads();
    for (int i = tid; i < rows * 32; i += 128)
        d_z2[base * 32 + i] = zs[(i >> 5) * 33 + (i & 31)];
    // BN partial sums over this tile
    int f = tid & 31;
    int r0 = tid >> 5;
    float s = 0.f, qq = 0.f;
    for (int r = r0; r < rows; r += 4) {
        float v = zs[r * 33 + f];
        s += v; qq += v * v;
    }
    atomicAdd(&ssum[f], s);
    atomicAdd(&ssq[f], qq);
    __syncthreads();
    if (tid < 32) atomicAdd(&d_bnstat[l * 64 + tid], ssum[tid]);
    else if (tid < 64) atomicAdd(&d_bnstat[l * 64 + tid], ssq[tid - 32]);
}

// -------- BN: finalize mean/var into scale/shift --------
__global__ void k_bnstat(int l, const float* __restrict__ g, const float* __restrict__ b) {
    int f = threadIdx.x;
    float s = d_bnstat[l * 64 + f];
    float q = d_bnstat[l * 64 + 32 + f];
    float mu = s / (float)NN;
    float var = q / (float)NN - mu * mu;
    float rs = rsqrtf(var + 1e-5f);
    float sc = g[l * 32 + f] * rs;
    d_bnscale[l * 64 + f] = sc;
    d_bnscale[l * 64 + 32 + f] = b[l * 32 + f] - mu * sc;
}

// -------- BN normalize + relu -> h (and z for next layer) --------
__global__ void k_bnnorm(int l, int write_z) {
    __shared__ float sc[32], sh[32];
    if (threadIdx.x < 32) {
        sc[threadIdx.x] = d_bnscale[l * 64 + threadIdx.x];
        sh[threadIdx.x] = d_bnscale[l * 64 + 32 + threadIdx.x];
    }
    __syncthreads();
    int i = blockIdx.x * blockDim.x + threadIdx.x;  // float4 index
    if (i >= NN * 8) return;
    float4 v = ((const float4*)d_z2)[i];
    int f0 = (i & 7) * 4;
    float4 r;
    r.x = fmaxf(0.f, v.x * sc[f0 + 0] + sh[f0 + 0]);
    r.y = fmaxf(0.f, v.y * sc[f0 + 1] + sh[f0 + 1]);
    r.z = fmaxf(0.f, v.z * sc[f0 + 2] + sh[f0 + 2]);
    r.w = fmaxf(0.f, v.w * sc[f0 + 3] + sh[f0 + 3]);
    ((float4*)d_h)[i] = r;
    if (write_z) ((float4*)d_z)[i] = r;
}

// -------- global mean pool (sums + counts) --------
__global__ void k_pool(const int* __restrict__ batch) {
    int t = blockIdx.x * blockDim.x + threadIdx.x;
    int n = t >> 3;
    if (n >= NN) return;
    int q = t & 7;
    int f0 = q * 4;
    int g = __ldg(batch + n);
    float4 v = *(const float4*)(d_h + n * 32 + f0);
    float* p = d_pool + g * 32 + f0;
    asm volatile("red.global.add.v4.f32 [%0], {%1,%2,%3,%4};"
                 :: "l"(p), "f"(v.x), "f"(v.y), "f"(v.z), "f"(v.w) : "memory");
    if (q == 0) atomicAdd(&d_cnt[g], 1.f);
}

// -------- readout head --------
__global__ void k_head(const float* __restrict__ w1, const float* __restrict__ b1,
                       const float* __restrict__ w2, const float* __restrict__ b2,
                       float* __restrict__ out) {
    __shared__ float W1[32 * 16];
    __shared__ float B1[16];
    __shared__ float W2[32];
    __shared__ float B2[2];
    for (int i = threadIdx.x; i < 512; i += blockDim.x) W1[i] = w1[i];
    if (threadIdx.x < 16) B1[threadIdx.x] = b1[threadIdx.x];
    if (threadIdx.x < 32) W2[threadIdx.x] = w2[threadIdx.x];
    if (threadIdx.x < 2) B2[threadIdx.x] = b2[threadIdx.x];
    __syncthreads();
    int g = blockIdx.x * blockDim.x + threadIdx.x;
    if (g >= NG) return;
    float inv = 1.f / fmaxf(d_cnt[g], 1.f);
    float gv[32];
#pragma unroll
    for (int k = 0; k < 32; k++) gv[k] = d_pool[g * 32 + k] * inv;
    float o0 = B2[0], o1 = B2[1];
#pragma unroll
    for (int j = 0; j < 16; j++) {
        float hj = B1[j];
#pragma unroll
        for (int k = 0; k < 32; k++) hj += gv[k] * W1[k * 16 + j];
        hj = fmaxf(hj, 0.f);
        o0 += hj * W2[j * 2 + 0];
        o1 += hj * W2[j * 2 + 1];
    }
    out[g * 2 + 0] = o0;
    out[g * 2 + 1] = o1;
}

extern "C" void kernel_launch(void* const* d_in, const int* in_sizes, int n_in,
                              void* d_out, int out_size) {
    const float* x    = (const float*)d_in[0];
    const int*   ei   = (const int*)  d_in[1];
    const float* ea   = (const float*)d_in[2];
    const int*   batch= (const int*)  d_in[3];
    const float* nw   = (const float*)d_in[4];
    const float* nb   = (const float*)d_in[5];
    const float* ew   = (const float*)d_in[6];
    const float* eb   = (const float*)d_in[7];
    const float* w1   = (const float*)d_in[8];
    const float* b1   = (const float*)d_in[9];
    const float* w2   = (const float*)d_in[10];
    const float* b2   = (const float*)d_in[11];
    const float* bng  = (const float*)d_in[12];
    const float* bnb  = (const float*)d_in[13];
    const float* l1w  = (const float*)d_in[14];
    const float* l1b  = (const float*)d_in[15];
    const float* l2w  = (const float*)d_in[16];
    const float* l2b  = (const float*)d_in[17];
    float* out = (float*)d_out;

    k_zero<<<256, 256>>>();
    k_embed<<<(NN + 255) / 256, 256>>>(x, nw, nb);
    for (int l = 0; l < 2; l++) {
        k_edge<<<(NE * 8) / 256, 256>>>(ei, ea, ew, eb);
        k_mlp<<<(NN + 127) / 128, 128>>>(l, w1, b1, w2, b2);
        k_bnstat<<<1, 32>>>(l, bng, bnb);
        k_bnnorm<<<(NN * 8 + 255) / 256, 256>>>(l, l == 0 ? 1 : 0);
    }
    k_pool<<<(NN * 8) / 256, 256>>>(batch);
    k_head<<<(NG + 255) / 256, 256>>>(l1w, l1b, l2w, l2b, out);
}

// round 2
// speedup vs baseline: 1.1928x; 1.1928x over previous
#include <cuda_runtime.h>

#define NN 200000
#define NE 2000000
#define NG 10000

typedef unsigned long long ull;

// -------- scratch (static device globals; no allocation) --------
__device__ float d_h[NN * 32];
__device__ float d_z[NN * 32];
__device__ float d_z2[NN * 32];
__device__ float d_pool[NG * 32];
__device__ float d_cnt[NG];
__device__ float d_bnstat[2 * 64];   // per layer: [sum(32) | sumsq(32)]
__device__ float d_bnscale[2 * 64];  // per layer: [scale(32) | shift(32)]

// -------- packed f32x2 helpers --------
__device__ __forceinline__ ull fma2(ull a, ull b, ull c) {
    ull d;
    asm("fma.rn.f32x2 %0, %1, %2, %3;" : "=l"(d) : "l"(a), "l"(b), "l"(c));
    return d;
}
__device__ __forceinline__ ull add2(ull a, ull b) {
    ull d;
    asm("add.rn.f32x2 %0, %1, %2;" : "=l"(d) : "l"(a), "l"(b));
    return d;
}
__device__ __forceinline__ float lo32(ull a) { return __uint_as_float((unsigned)a); }
__device__ __forceinline__ float hi32(ull a) { return __uint_as_float((unsigned)(a >> 32)); }
__device__ __forceinline__ ull pack2(float x, float y) {
    ull r;
    asm("mov.b64 %0, {%1, %2};" : "=l"(r) : "f"(x), "f"(y));
    return r;
}

// -------- zero accumulators --------
__global__ void k_zero() {
    int i = blockIdx.x * blockDim.x + threadIdx.x;
    const int n = NG * 32 + NG + 2 * 64;
    for (; i < n; i += gridDim.x * blockDim.x) {
        if (i < NG * 32) d_pool[i] = 0.f;
        else if (i < NG * 32 + NG) d_cnt[i - NG * 32] = 0.f;
        else d_bnstat[i - NG * 32 - NG] = 0.f;
    }
}

// -------- node embedding: h = x @ node_w + node_b ; also z = h --------
__global__ void k_embed(const float* __restrict__ x,
                        const float* __restrict__ nw,
                        const float* __restrict__ nb) {
    __shared__ float w[14 * 32];
    __shared__ float b[32];
    for (int i = threadIdx.x; i < 448; i += blockDim.x) w[i] = nw[i];
    if (threadIdx.x < 32) b[threadIdx.x] = nb[threadIdx.x];
    __syncthreads();
    int n = blockIdx.x * blockDim.x + threadIdx.x;
    if (n >= NN) return;
    float xv[14];
#pragma unroll
    for (int k = 0; k < 14; k++) xv[k] = x[n * 14 + k];
#pragma unroll
    for (int f = 0; f < 32; f++) {
        float o = b[f];
#pragma unroll
        for (int k = 0; k < 14; k++) o += xv[k] * w[k * 32 + f];
        d_h[n * 32 + f] = o;
        d_z[n * 32 + f] = o;
    }
}

// -------- edge messages: z[dst] += relu(h[src] + attr@ew + eb) --------
// 8 lanes per edge; lane 0 of each group loads indices/attrs, shfl-broadcast.
__global__ void k_edge(const int* __restrict__ ei,
                       const float* __restrict__ ea,
                       const float* __restrict__ ew,
                       const float* __restrict__ eb) {
    __shared__ float w[96];
    __shared__ float b[32];
    for (int i = threadIdx.x; i < 96; i += blockDim.x) w[i] = ew[i];
    if (threadIdx.x < 32) b[threadIdx.x] = eb[threadIdx.x];
    __syncthreads();
    int t = blockIdx.x * blockDim.x + threadIdx.x;
    int e = t >> 3;
    int lane = threadIdx.x & 31;
    int base = lane & ~7;            // leader lane of this 8-lane group
    int q = t & 7;
    int f0 = q * 4;
    int src = 0, dst = 0;
    float a0 = 0.f, a1 = 0.f, a2 = 0.f;
    if (q == 0) {
        src = __ldg(ei + e);
        dst = __ldg(ei + NE + e);
        a0 = __ldg(ea + e * 3 + 0);
        a1 = __ldg(ea + e * 3 + 1);
        a2 = __ldg(ea + e * 3 + 2);
    }
    src = __shfl_sync(0xffffffffu, src, base);
    dst = __shfl_sync(0xffffffffu, dst, base);
    a0  = __shfl_sync(0xffffffffu, a0, base);
    a1  = __shfl_sync(0xffffffffu, a1, base);
    a2  = __shfl_sync(0xffffffffu, a2, base);
    float4 hv = *(const float4*)(d_h + src * 32 + f0);
    float m0 = fmaxf(0.f, hv.x + b[f0 + 0] + a0 * w[f0 + 0] + a1 * w[32 + f0 + 0] + a2 * w[64 + f0 + 0]);
    float m1 = fmaxf(0.f, hv.y + b[f0 + 1] + a0 * w[f0 + 1] + a1 * w[32 + f0 + 1] + a2 * w[64 + f0 + 1]);
    float m2 = fmaxf(0.f, hv.z + b[f0 + 2] + a0 * w[f0 + 2] + a1 * w[32 + f0 + 2] + a2 * w[64 + f0 + 2]);
    float m3 = fmaxf(0.f, hv.w + b[f0 + 3] + a0 * w[f0 + 3] + a1 * w[32 + f0 + 3] + a2 * w[64 + f0 + 3]);
    float* p = d_z + dst * 32 + f0;
    asm volatile("red.global.add.v4.f32 [%0], {%1,%2,%3,%4};"
                 :: "l"(p), "f"(m0), "f"(m1), "f"(m2), "f"(m3) : "memory");
}

// -------- MLP: z2 = relu(z@W1+b1)@W2+b2, fused BN partial sums --------
// Packed fma.rn.f32x2 + vector LDS.128; W1 transposed in smem.
__global__ void __launch_bounds__(128) k_mlp(int l,
        const float* __restrict__ w1, const float* __restrict__ b1,
        const float* __restrict__ w2, const float* __restrict__ b2) {
    __shared__ float W1t[75 * 32];   // row j: W1[:,j], 32 contiguous floats
    __shared__ float W2s[75 * 32];   // row j: W2[j,:], 32 contiguous floats
    __shared__ float B1[75];
    __shared__ float zs[128 * 33];
    __shared__ float ssum[32], ssq[32];
    const float* w1l = w1 + l * 2400;
    const float* w2l = w2 + l * 2400;
    for (int i = threadIdx.x; i < 2400; i += 128) {
        W1t[(i % 75) * 32 + (i / 75)] = w1l[i];   // transpose (32,75)->(75,32)
        W2s[i] = w2l[i];
    }
    for (int i = threadIdx.x; i < 75; i += 128) B1[i] = b1[l * 75 + i];
    if (threadIdx.x < 32) { ssum[threadIdx.x] = 0.f; ssq[threadIdx.x] = 0.f; }
    __syncthreads();

    int tid = threadIdx.x;
    int base = blockIdx.x * 128;
    int rows = min(128, NN - base);
    ull acc[16];
    if (tid < rows) {
        int row = base + tid;
        // load z row as 16 packed f32x2
        ull zp[16];
        const ulonglong2* zrow = (const ulonglong2*)(d_z + row * 32);
#pragma unroll
        for (int i = 0; i < 8; i++) {
            ulonglong2 v = zrow[i];
            zp[i * 2] = v.x; zp[i * 2 + 1] = v.y;
        }
#pragma unroll
        for (int t = 0; t < 16; t++)
            acc[t] = pack2(__ldg(b2 + l * 32 + 2 * t), __ldg(b2 + l * 32 + 2 * t + 1));
#pragma unroll 5
        for (int j = 0; j < 75; j++) {
            const ulonglong2* w1r = (const ulonglong2*)(W1t + j * 32);
            ull h0 = pack2(B1[j], 0.f), h1 = 0, h2 = 0, h3 = 0;
#pragma unroll
            for (int i = 0; i < 4; i++) {
                ulonglong2 wa = w1r[i * 2];
                ulonglong2 wb = w1r[i * 2 + 1];
                h0 = fma2(zp[i * 4 + 0], wa.x, h0);
                h1 = fma2(zp[i * 4 + 1], wa.y, h1);
                h2 = fma2(zp[i * 4 + 2], wb.x, h2);
                h3 = fma2(zp[i * 4 + 3], wb.y, h3);
            }
            ull s = add2(add2(h0, h1), add2(h2, h3));
            float hj = fmaxf(0.f, lo32(s) + hi32(s));
            ull hb = pack2(hj, hj);
            const ulonglong2* w2r = (const ulonglong2*)(W2s + j * 32);
#pragma unroll
            for (int i = 0; i < 8; i++) {
                ulonglong2 wv = w2r[i];
                acc[i * 2] = fma2(hb, wv.x, acc[i * 2]);
                acc[i * 2 + 1] = fma2(hb, wv.y, acc[i * 2 + 1]);
            }
        }
        // write output directly (coalesced enough: 128B contiguous per thread)
        ulonglong2* orow = (ulonglong2*)(d_z2 + row * 32);
#pragma unroll
        for (int i = 0; i < 8; i++) {
            ulonglong2 v;
            v.x = acc[i * 2]; v.y = acc[i * 2 + 1];
            orow[i] = v;
        }
        // stage into smem for BN reduction
#pragma unroll
        for (int t = 0; t < 16; t++) {
            zs[tid * 33 + 2 * t] = lo32(acc[t]);
            zs[tid * 33 + 2 * t + 1] = hi32(acc[t]);
        }
    }
    __syncthreads();
    // BN partial sums over this tile
    int f = tid & 31;
    int r0 = tid >> 5;
    float s = 0.f, qq = 0.f;
    for (int r = r0; r < rows; r += 4) {
        float v = zs[r * 33 + f];
        s += v; qq += v * v;
    }
    atomicAdd(&ssum[f], s);
    atomicAdd(&ssq[f], qq);
    __syncthreads();
    if (tid < 32) atomicAdd(&d_bnstat[l * 64 + tid], ssum[tid]);
    else if (tid < 64) atomicAdd(&d_bnstat[l * 64 + tid], ssq[tid - 32]);
}

// -------- BN: finalize mean/var into scale/shift --------
__global__ void k_bnstat(int l, const float* __restrict__ g, const float* __restrict__ b) {
    int f = threadIdx.x;
    float s = d_bnstat[l * 64 + f];
    float q = d_bnstat[l * 64 + 32 + f];
    float mu = s / (float)NN;
    float var = q / (float)NN - mu * mu;
    float rs = rsqrtf(var + 1e-5f);
    float sc = g[l * 32 + f] * rs;
    d_bnscale[l * 64 + f] = sc;
    d_bnscale[l * 64 + 32 + f] = b[l * 32 + f] - mu * sc;
}

// -------- BN normalize + relu; mode 0: write h+z; mode 1: fused pool --------
__global__ void k_bnnorm(int l, int mode, const int* __restrict__ batch) {
    __shared__ float sc[32], sh[32];
    if (threadIdx.x < 32) {
        sc[threadIdx.x] = d_bnscale[l * 64 + threadIdx.x];
        sh[threadIdx.x] = d_bnscale[l * 64 + 32 + threadIdx.x];
    }
    __syncthreads();
    int i = blockIdx.x * blockDim.x + threadIdx.x;  // float4 index
    if (i >= NN * 8) return;
    float4 v = ((const float4*)d_z2)[i];
    int f0 = (i & 7) * 4;
    float4 r;
    r.x = fmaxf(0.f, v.x * sc[f0 + 0] + sh[f0 + 0]);
    r.y = fmaxf(0.f, v.y * sc[f0 + 1] + sh[f0 + 1]);
    r.z = fmaxf(0.f, v.z * sc[f0 + 2] + sh[f0 + 2]);
    r.w = fmaxf(0.f, v.w * sc[f0 + 3] + sh[f0 + 3]);
    if (mode == 0) {
        ((float4*)d_h)[i] = r;
        ((float4*)d_z)[i] = r;
    } else {
        // fused global mean pool accumulation (skip writing h entirely)
        int n = i >> 3;
        int g = __ldg(batch + n);
        float* p = d_pool + g * 32 + f0;
        asm volatile("red.global.add.v4.f32 [%0], {%1,%2,%3,%4};"
                     :: "l"(p), "f"(r.x), "f"(r.y), "f"(r.z), "f"(r.w) : "memory");
        if ((i & 7) == 0) atomicAdd(&d_cnt[g], 1.f);
    }
}

// -------- readout head --------
__global__ void k_head(const float* __restrict__ w1, const float* __restrict__ b1,
                       const float* __restrict__ w2, const float* __restrict__ b2,
                       float* __restrict__ out) {
    __shared__ float W1[32 * 16];
    __shared__ float B1[16];
    __shared__ float W2[32];
    __shared__ float B2[2];
    for (int i = threadIdx.x; i < 512; i += blockDim.x) W1[i] = w1[i];
    if (threadIdx.x < 16) B1[threadIdx.x] = b1[threadIdx.x];
    if (threadIdx.x < 32) W2[threadIdx.x] = w2[threadIdx.x];
    if (threadIdx.x < 2) B2[threadIdx.x] = b2[threadIdx.x];
    __syncthreads();
    int g = blockIdx.x * blockDim.x + threadIdx.x;
    if (g >= NG) return;
    float inv = 1.f / fmaxf(d_cnt[g], 1.f);
    float gv[32];
#pragma unroll
    for (int k = 0; k < 32; k++) gv[k] = d_pool[g * 32 + k] * inv;
    float o0 = B2[0], o1 = B2[1];
#pragma unroll
    for (int j = 0; j < 16; j++) {
        float hj = B1[j];
#pragma unroll
        for (int k = 0; k < 32; k++) hj += gv[k] * W1[k * 16 + j];
        hj = fmaxf(hj, 0.f);
        o0 += hj * W2[j * 2 + 0];
        o1 += hj * W2[j * 2 + 1];
    }
    out[g * 2 + 0] = o0;
    out[g * 2 + 1] = o1;
}

extern "C" void kernel_launch(void* const* d_in, const int* in_sizes, int n_in,
                              void* d_out, int out_size) {
    const float* x    = (const float*)d_in[0];
    const int*   ei   = (const int*)  d_in[1];
    const float* ea   = (const float*)d_in[2];
    const int*   batch= (const int*)  d_in[3];
    const float* nw   = (const float*)d_in[4];
    const float* nb   = (const float*)d_in[5];
    const float* ew   = (const float*)d_in[6];
    const float* eb   = (const float*)d_in[7];
    const float* w1   = (const float*)d_in[8];
    const float* b1   = (const float*)d_in[9];
    const float* w2   = (const float*)d_in[10];
    const float* b2   = (const float*)d_in[11];
    const float* bng  = (const float*)d_in[12];
    const float* bnb  = (const float*)d_in[13];
    const float* l1w  = (const float*)d_in[14];
    const float* l1b  = (const float*)d_in[15];
    const float* l2w  = (const float*)d_in[16];
    const float* l2b  = (const float*)d_in[17];
    float* out = (float*)d_out;

    k_zero<<<256, 256>>>();
    k_embed<<<(NN + 255) / 256, 256>>>(x, nw, nb);
    for (int l = 0; l < 2; l++) {
        k_edge<<<(NE * 8) / 256, 256>>>(ei, ea, ew, eb);
        k_mlp<<<(NN + 127) / 128, 128>>>(l, w1, b1, w2, b2);
        k_bnstat<<<1, 32>>>(l, bng, bnb);
        k_bnnorm<<<(NN * 8 + 255) / 256, 256>>>(l, l == 0 ? 0 : 1, batch);
    }
    k_head<<<(NG + 255) / 256, 256>>>(l1w, l1b, l2w, l2b, out);
}